// round 2
// baseline (speedup 1.0000x reference)
#include <cuda_runtime.h>
#include <math.h>
#include <stdint.h>

// ---------------- problem constants ----------------
#define KB   16          // batch
#define KG   2048        // group count
#define KC   384         // channels
#define KH   6           // heads
#define KDH  64          // head dim
#define KV   820         // visible tokens per row
#define KDEPTH 6
#define KBV  (KB*KV)     // 13120 rows
#define KR2  0.16f       // radius^2

// ---------------- static device scratch (no allocs allowed) ----------------
__device__ float g_bufA[KBV*KC];
__device__ float g_bufB[KBV*KC];
__device__ float g_pos [KBV*KC];
__device__ float g_hn  [KBV*KC];
__device__ float g_qkv [KBV*3*KC];
__device__ float g_obuf[KBV*KC];
__device__ float g_t4  [KBV*4*KC];
__device__ float g_ctr [KBV*3];
__device__ int   g_order[KBV];

// ---------------- helpers ----------------
__device__ __forceinline__ float gelu_tanh(float x) {
    const float c = 0.7978845608028654f;
    float inner = c * (x + 0.044715f * x * x * x);
    return 0.5f * x * (1.0f + tanhf(inner));
}

__device__ __forceinline__ float blockReduceSum(float val) {
    __shared__ float sh[4];
    __shared__ float tot;
    __syncthreads();                      // protect reuse across calls
    int lane = threadIdx.x & 31;
    int wid  = threadIdx.x >> 5;
    #pragma unroll
    for (int o = 16; o; o >>= 1) val += __shfl_down_sync(0xffffffffu, val, o);
    if (lane == 0) sh[wid] = val;
    __syncthreads();
    if (threadIdx.x == 0) tot = sh[0] + sh[1] + sh[2] + sh[3];
    __syncthreads();
    return tot;
}

// ---------------- ragged pack: build visible-token order ----------------
// mask dtype is unknown (bool/u8 vs int32 vs float32). Detect per row:
// if the u8 interpretation of this row has exactly KV zero bytes, it's u8;
// otherwise interpret 4-byte words (covers int32 AND float32, since any
// nonzero float has nonzero bits).
__global__ void build_order_kernel(const void* mask, int* order) {
    int b = blockIdx.x;
    if (threadIdx.x != 0) return;
    const unsigned char* m8 = (const unsigned char*)mask;
    int zc = 0;
    for (int i = 0; i < KG; i++) zc += (m8[(size_t)b*KG + i] == 0);
    int cnt = 0;
    if (zc == KV) {
        for (int i = 0; i < KG && cnt < KV; i++)
            if (m8[(size_t)b*KG + i] == 0) order[b*KV + cnt++] = i;
    } else {
        const int* m32 = (const int*)mask;
        for (int i = 0; i < KG && cnt < KV; i++)
            if (m32[(size_t)b*KG + i] == 0) order[b*KV + cnt++] = i;
    }
}

__global__ void gather_kernel(const float* __restrict__ tokens,
                              const float* __restrict__ centers,
                              const int* __restrict__ order,
                              float* __restrict__ x, float* __restrict__ ctr) {
    int bv = blockIdx.x;
    int b = bv / KV;
    int src = order[bv];
    int tid = threadIdx.x;  // 384
    x[(size_t)bv*KC + tid] = tokens[((size_t)b*KG + src)*KC + tid];
    if (tid < 3) ctr[(size_t)bv*3 + tid] = centers[((size_t)b*KG + src)*3 + tid];
}

// ---------------- tiled SGEMM: C = act(A[M,K] @ W[K,N] + bias) (+= C) ----------------
__global__ void gemm_kernel(const float* __restrict__ A, const float* __restrict__ W,
                            const float* __restrict__ bias, float* __restrict__ C,
                            int M, int K, int N, int act, int addC) {
    __shared__ float As[16][65];
    __shared__ float Bs[16][65];
    const int tid = threadIdx.x;      // 256 threads
    const int tx = tid & 15;
    const int ty = tid >> 4;
    const int bm = blockIdx.y * 64;
    const int bn = blockIdx.x * 64;
    float acc[4][4];
    #pragma unroll
    for (int i = 0; i < 4; i++)
        #pragma unroll
        for (int j = 0; j < 4; j++) acc[i][j] = 0.f;

    for (int k0 = 0; k0 < K; k0 += 16) {
        #pragma unroll
        for (int t = 0; t < 4; t++) {
            int idx = tid + t * 256;      // 0..1023
            int m  = idx >> 4;
            int kk = idx & 15;
            int gm = bm + m, gk = k0 + kk;
            float v = 0.f;
            if (gk < K && gm < M) v = A[(size_t)gm * K + gk];
            As[kk][m] = v;
        }
        #pragma unroll
        for (int t = 0; t < 4; t++) {
            int idx = tid + t * 256;
            int kk = idx >> 6;
            int n  = idx & 63;
            int gk = k0 + kk, gn = bn + n;
            float v = 0.f;
            if (gk < K && gn < N) v = W[(size_t)gk * N + gn];
            Bs[kk][n] = v;
        }
        __syncthreads();
        #pragma unroll
        for (int kk = 0; kk < 16; kk++) {
            float a[4], b[4];
            #pragma unroll
            for (int i = 0; i < 4; i++) a[i] = As[kk][ty*4 + i];
            #pragma unroll
            for (int j = 0; j < 4; j++) b[j] = Bs[kk][tx*4 + j];
            #pragma unroll
            for (int i = 0; i < 4; i++)
                #pragma unroll
                for (int j = 0; j < 4; j++)
                    acc[i][j] = fmaf(a[i], b[j], acc[i][j]);
        }
        __syncthreads();
    }
    #pragma unroll
    for (int i = 0; i < 4; i++) {
        int gm = bm + ty*4 + i;
        if (gm >= M) continue;
        #pragma unroll
        for (int j = 0; j < 4; j++) {
            int gn = bn + tx*4 + j;
            if (gn >= N) continue;
            float v = acc[i][j] + bias[gn];
            if (act) v = gelu_tanh(v);
            size_t off = (size_t)gm * N + gn;
            if (addC) v += C[off];
            C[off] = v;
        }
    }
}

// ---------------- LayerNorm (optional "+pos" fuse, optional h output) ----------------
__global__ void ln_kernel(const float* __restrict__ x, const float* __restrict__ pos,
                          float* __restrict__ hout, float* __restrict__ hn,
                          const float* __restrict__ w, const float* __restrict__ bb) {
    int row = blockIdx.x;
    int tid = threadIdx.x;       // 128 threads, 3 elems each
    size_t base = (size_t)row * KC;
    float v[3];
    #pragma unroll
    for (int i = 0; i < 3; i++) {
        int c = tid + i * 128;
        float t = x[base + c];
        if (pos) t += pos[base + c];
        v[i] = t;
        if (hout) hout[base + c] = t;
    }
    float s = blockReduceSum(v[0] + v[1] + v[2]);
    float mean = s * (1.0f / KC);
    float d0 = v[0] - mean, d1 = v[1] - mean, d2 = v[2] - mean;
    float s2 = blockReduceSum(d0*d0 + d1*d1 + d2*d2);
    float inv = rsqrtf(s2 * (1.0f / KC) + 1e-5f);
    #pragma unroll
    for (int i = 0; i < 3; i++) {
        int c = tid + i * 128;
        hn[base + c] = (v[i] - mean) * inv * w[c] + bb[c];
    }
}

// ---------------- fused masked flash attention ----------------
// qkv layout per row: [3][H][64]. Grid: (ceil(V/64), H, B). Block: 64 threads,
// one query row per thread. Online softmax; mask = (dist^2 >= 0.16) skipped.
__global__ void attn_kernel(const float* __restrict__ qkv,
                            const float* __restrict__ ctr,
                            float* __restrict__ o) {
    const int qt = blockIdx.x, h = blockIdx.y, b = blockIdx.z;
    const int tid = threadIdx.x;
    const int qi = qt * 64 + tid;
    const bool valid = (qi < KV);

    __shared__ __align__(16) float ks[64][64];
    __shared__ __align__(16) float vs[64][64];
    __shared__ float kc[64][3];

    const int qrow = valid ? qi : 0;
    const size_t qbase = ((size_t)b * KV + qrow) * (3*KC) + h * KDH;
    float q[64];
    {
        const float4* q4 = reinterpret_cast<const float4*>(qkv + qbase);
        #pragma unroll
        for (int d4 = 0; d4 < 16; d4++) {
            float4 t = q4[d4];
            q[d4*4+0] = t.x * 0.125f;   // fold dh^-0.5 = 1/8 (exact)
            q[d4*4+1] = t.y * 0.125f;
            q[d4*4+2] = t.z * 0.125f;
            q[d4*4+3] = t.w * 0.125f;
        }
    }
    float qc0 = ctr[((size_t)b*KV + qrow)*3 + 0];
    float qc1 = ctr[((size_t)b*KV + qrow)*3 + 1];
    float qc2 = ctr[((size_t)b*KV + qrow)*3 + 2];

    float m = -3.4e38f, l = 0.f;
    float oacc[64];
    #pragma unroll
    for (int d = 0; d < 64; d++) oacc[d] = 0.f;

    const int ntiles = (KV + 63) / 64;
    for (int kt = 0; kt < ntiles; kt++) {
        const int cnt = min(64, KV - kt * 64);
        // cooperative K/V tile load (float4, coalesced)
        #pragma unroll 4
        for (int it = 0; it < 16; it++) {
            int idx = tid + it * 64;      // 0..1023 (j,d4)
            int j  = idx >> 4;
            int d4 = idx & 15;
            if (j < cnt) {
                size_t kb = ((size_t)b * KV + kt*64 + j) * (3*KC) + h * KDH;
                const float4* p4 = reinterpret_cast<const float4*>(qkv);
                float4 kvv = p4[kb/4 + KC/4 + d4];       // +384 floats
                float4 vvv = p4[kb/4 + 2*KC/4 + d4];     // +768 floats
                reinterpret_cast<float4*>(ks[j])[d4] = kvv;
                reinterpret_cast<float4*>(vs[j])[d4] = vvv;
            }
        }
        if (tid < cnt) {
            size_t cb = ((size_t)b*KV + kt*64 + tid) * 3;
            kc[tid][0] = ctr[cb + 0];
            kc[tid][1] = ctr[cb + 1];
            kc[tid][2] = ctr[cb + 2];
        }
        __syncthreads();

        if (valid) {
            for (int j = 0; j < cnt; j++) {
                float dx = qc0 - kc[j][0];
                float dy = qc1 - kc[j][1];
                float dz = qc2 - kc[j][2];
                float d2 = dx*dx + dy*dy + dz*dz;
                if (d2 < KR2) {
                    const float4* kr = reinterpret_cast<const float4*>(ks[j]);
                    float s0 = 0.f, s1 = 0.f, s2 = 0.f, s3 = 0.f;
                    #pragma unroll
                    for (int d4 = 0; d4 < 16; d4++) {
                        float4 kk = kr[d4];
                        s0 = fmaf(q[d4*4+0], kk.x, s0);
                        s1 = fmaf(q[d4*4+1], kk.y, s1);
                        s2 = fmaf(q[d4*4+2], kk.z, s2);
                        s3 = fmaf(q[d4*4+3], kk.w, s3);
                    }
                    float s = (s0 + s1) + (s2 + s3);
                    if (s > m) {
                        float corr = __expf(m - s);
                        l *= corr;
                        #pragma unroll
                        for (int d = 0; d < 64; d++) oacc[d] *= corr;
                        m = s;
                    }
                    float p = __expf(s - m);
                    l += p;
                    const float4* vr = reinterpret_cast<const float4*>(vs[j]);
                    #pragma unroll
                    for (int d4 = 0; d4 < 16; d4++) {
                        float4 vv = vr[d4];
                        oacc[d4*4+0] = fmaf(p, vv.x, oacc[d4*4+0]);
                        oacc[d4*4+1] = fmaf(p, vv.y, oacc[d4*4+1]);
                        oacc[d4*4+2] = fmaf(p, vv.z, oacc[d4*4+2]);
                        oacc[d4*4+3] = fmaf(p, vv.w, oacc[d4*4+3]);
                    }
                }
            }
        }
        __syncthreads();
    }

    if (valid) {
        float inv = 1.0f / l;    // self-attention always unmasked -> l > 0
        size_t ob = ((size_t)b*KV + qi) * KC + h * KDH;
        #pragma unroll
        for (int d = 0; d < 64; d++) o[ob + d] = oacc[d] * inv;
    }
}

// ---------------- launcher ----------------
extern "C" void kernel_launch(void* const* d_in, const int* in_sizes, int n_in,
                              void* d_out, int out_size) {
    const float* tokens  = (const float*)d_in[0];
    const float* centers = (const float*)d_in[1];
    const void*  mask    = d_in[2];
    const float* pos_w1  = (const float*)d_in[3];
    const float* pos_b1  = (const float*)d_in[4];
    const float* pos_w2  = (const float*)d_in[5];
    const float* pos_b2  = (const float*)d_in[6];
    const float* ln1_w   = (const float*)d_in[7];
    const float* ln1_b   = (const float*)d_in[8];
    const float* qkv_w   = (const float*)d_in[9];
    const float* qkv_b   = (const float*)d_in[10];
    const float* proj_w  = (const float*)d_in[11];
    const float* proj_b  = (const float*)d_in[12];
    const float* ln2_w   = (const float*)d_in[13];
    const float* ln2_b   = (const float*)d_in[14];
    const float* fc1_w   = (const float*)d_in[15];
    const float* fc1_b   = (const float*)d_in[16];
    const float* fc2_w   = (const float*)d_in[17];
    const float* fc2_b   = (const float*)d_in[18];
    const float* lnf_w   = (const float*)d_in[19];
    const float* lnf_b   = (const float*)d_in[20];

    float *bufA, *bufB, *pos, *hn, *qkv, *obuf, *t4, *ctr;
    int* order;
    cudaGetSymbolAddress((void**)&bufA,  g_bufA);
    cudaGetSymbolAddress((void**)&bufB,  g_bufB);
    cudaGetSymbolAddress((void**)&pos,   g_pos);
    cudaGetSymbolAddress((void**)&hn,    g_hn);
    cudaGetSymbolAddress((void**)&qkv,   g_qkv);
    cudaGetSymbolAddress((void**)&obuf,  g_obuf);
    cudaGetSymbolAddress((void**)&t4,    g_t4);
    cudaGetSymbolAddress((void**)&ctr,   g_ctr);
    cudaGetSymbolAddress((void**)&order, g_order);

    const int M = KBV;              // 13120, multiple of 64
    const dim3 blk(256);
    const int gy = M / 64;          // 205

    // ragged pack
    build_order_kernel<<<KB, 32>>>(mask, order);
    gather_kernel<<<KBV, KC>>>(tokens, centers, order, bufA, ctr);

    // positional MLP: pos = gelu(ctr @ pos_w1 + b1) @ pos_w2 + b2
    gemm_kernel<<<dim3(KC/64, gy), blk>>>(ctr, pos_w1, pos_b1, hn,  M, 3,  KC, 1, 0);
    gemm_kernel<<<dim3(KC/64, gy), blk>>>(hn,  pos_w2, pos_b2, pos, M, KC, KC, 0, 0);

    float* cur = bufA;
    float* oth = bufB;
    for (int l = 0; l < KDEPTH; l++) {
        // h = x + pos ; hn = LN1(h)
        ln_kernel<<<KBV, 128>>>(cur, pos, oth, hn, ln1_w + l*KC, ln1_b + l*KC);
        // qkv = hn @ Wqkv + b
        gemm_kernel<<<dim3(3*KC/64, gy), blk>>>(hn, qkv_w + (size_t)l*KC*3*KC,
                                                qkv_b + (size_t)l*3*KC, qkv,
                                                M, KC, 3*KC, 0, 0);
        // masked attention -> obuf
        attn_kernel<<<dim3((KV+63)/64, KH, KB), 64>>>(qkv, ctr, obuf);
        // h += obuf @ Wproj + b
        gemm_kernel<<<dim3(KC/64, gy), blk>>>(obuf, proj_w + (size_t)l*KC*KC,
                                              proj_b + (size_t)l*KC, oth,
                                              M, KC, KC, 0, 1);
        // hn = LN2(h)
        ln_kernel<<<KBV, 128>>>(oth, nullptr, nullptr, hn, ln2_w + l*KC, ln2_b + l*KC);
        // t4 = gelu(hn @ W1 + b1)
        gemm_kernel<<<dim3(4*KC/64, gy), blk>>>(hn, fc1_w + (size_t)l*KC*4*KC,
                                                fc1_b + (size_t)l*4*KC, t4,
                                                M, KC, 4*KC, 1, 0);
        // h += t4 @ W2 + b2
        gemm_kernel<<<dim3(KC/64, gy), blk>>>(t4, fc2_w + (size_t)l*4*KC*KC,
                                              fc2_b + (size_t)l*KC, oth,
                                              M, 4*KC, KC, 0, 1);
        float* tmp = cur; cur = oth; oth = tmp;
    }
    // final LN -> output [B, V, C] f32
    ln_kernel<<<KBV, 128>>>(cur, nullptr, nullptr, (float*)d_out, lnf_w, lnf_b);
}

// round 3
// speedup vs baseline: 1.8300x; 1.8300x over previous
#include <cuda_runtime.h>
#include <math.h>
#include <stdint.h>

// ---------------- problem constants ----------------
#define KB   16          // batch
#define KG   2048        // group count
#define KC   384         // channels
#define KH   6           // heads
#define KDH  64          // head dim
#define KV   820         // visible tokens per row
#define KDEPTH 6
#define KBV  (KB*KV)     // 13120 rows
#define KR2  0.16f       // radius^2

// ---------------- static device scratch (no allocs allowed) ----------------
__device__ float g_bufA[KBV*KC];
__device__ float g_bufB[KBV*KC];
__device__ float g_pos [KBV*KC];
__device__ float g_hn  [KBV*KC];
__device__ float g_qkv [KBV*3*KC];
__device__ float g_obuf[KBV*KC];
__device__ float g_t4  [KBV*4*KC];
__device__ float g_ctr [KBV*3];
__device__ int   g_order[KBV];

// ---------------- helpers ----------------
__device__ __forceinline__ float gelu_tanh(float x) {
    const float c = 0.7978845608028654f;
    float inner = c * (x + 0.044715f * x * x * x);
    return 0.5f * x * (1.0f + tanhf(inner));
}

__device__ __forceinline__ float blockReduceSum(float val) {
    __shared__ float sh[4];
    __shared__ float tot;
    __syncthreads();
    int lane = threadIdx.x & 31;
    int wid  = threadIdx.x >> 5;
    #pragma unroll
    for (int o = 16; o; o >>= 1) val += __shfl_down_sync(0xffffffffu, val, o);
    if (lane == 0) sh[wid] = val;
    __syncthreads();
    if (threadIdx.x == 0) tot = sh[0] + sh[1] + sh[2] + sh[3];
    __syncthreads();
    return tot;
}

// tf32 round-to-nearest (cvt.rna), result kept as f32 bit pattern
__device__ __forceinline__ float tf32r(float x) {
    unsigned u;
    asm("cvt.rna.tf32.f32 %0, %1;" : "=r"(u) : "f"(x));
    return __uint_as_float(u);
}

__device__ __forceinline__ void mma_tf32(float* d, const unsigned* a,
                                         const unsigned* b) {
    asm volatile(
        "mma.sync.aligned.m16n8k8.row.col.f32.tf32.tf32.f32 "
        "{%0,%1,%2,%3}, {%4,%5,%6,%7}, {%8,%9}, {%0,%1,%2,%3};\n"
        : "+f"(d[0]), "+f"(d[1]), "+f"(d[2]), "+f"(d[3])
        : "r"(a[0]), "r"(a[1]), "r"(a[2]), "r"(a[3]),
          "r"(b[0]), "r"(b[1]));
}

// ---------------- ragged pack ----------------
__global__ void build_order_kernel(const void* mask, int* order) {
    int b = blockIdx.x;
    if (threadIdx.x != 0) return;
    const unsigned char* m8 = (const unsigned char*)mask;
    int zc = 0;
    for (int i = 0; i < KG; i++) zc += (m8[(size_t)b*KG + i] == 0);
    int cnt = 0;
    if (zc == KV) {
        for (int i = 0; i < KG && cnt < KV; i++)
            if (m8[(size_t)b*KG + i] == 0) order[b*KV + cnt++] = i;
    } else {
        const int* m32 = (const int*)mask;
        for (int i = 0; i < KG && cnt < KV; i++)
            if (m32[(size_t)b*KG + i] == 0) order[b*KV + cnt++] = i;
    }
}

__global__ void gather_kernel(const float* __restrict__ tokens,
                              const float* __restrict__ centers,
                              const int* __restrict__ order,
                              float* __restrict__ x, float* __restrict__ ctr) {
    int bv = blockIdx.x;
    int b = bv / KV;
    int src = order[bv];
    int tid = threadIdx.x;  // 384
    x[(size_t)bv*KC + tid] = tokens[((size_t)b*KG + src)*KC + tid];
    if (tid < 3) ctr[(size_t)bv*3 + tid] = centers[((size_t)b*KG + src)*3 + tid];
}

// ---------------- FFMA GEMM (kept for tiny-K pos MLP layer 1) ----------------
__global__ void gemm_kernel(const float* __restrict__ A, const float* __restrict__ W,
                            const float* __restrict__ bias, float* __restrict__ C,
                            int M, int K, int N, int act, int addC) {
    __shared__ float As[16][65];
    __shared__ float Bs[16][65];
    const int tid = threadIdx.x;
    const int tx = tid & 15;
    const int ty = tid >> 4;
    const int bm = blockIdx.y * 64;
    const int bn = blockIdx.x * 64;
    float acc[4][4];
    #pragma unroll
    for (int i = 0; i < 4; i++)
        #pragma unroll
        for (int j = 0; j < 4; j++) acc[i][j] = 0.f;

    for (int k0 = 0; k0 < K; k0 += 16) {
        #pragma unroll
        for (int t = 0; t < 4; t++) {
            int idx = tid + t * 256;
            int m  = idx >> 4;
            int kk = idx & 15;
            int gm = bm + m, gk = k0 + kk;
            float v = 0.f;
            if (gk < K && gm < M) v = A[(size_t)gm * K + gk];
            As[kk][m] = v;
        }
        #pragma unroll
        for (int t = 0; t < 4; t++) {
            int idx = tid + t * 256;
            int kk = idx >> 6;
            int n  = idx & 63;
            int gk = k0 + kk, gn = bn + n;
            float v = 0.f;
            if (gk < K && gn < N) v = W[(size_t)gk * N + gn];
            Bs[kk][n] = v;
        }
        __syncthreads();
        #pragma unroll
        for (int kk = 0; kk < 16; kk++) {
            float a[4], b[4];
            #pragma unroll
            for (int i = 0; i < 4; i++) a[i] = As[kk][ty*4 + i];
            #pragma unroll
            for (int j = 0; j < 4; j++) b[j] = Bs[kk][tx*4 + j];
            #pragma unroll
            for (int i = 0; i < 4; i++)
                #pragma unroll
                for (int j = 0; j < 4; j++)
                    acc[i][j] = fmaf(a[i], b[j], acc[i][j]);
        }
        __syncthreads();
    }
    #pragma unroll
    for (int i = 0; i < 4; i++) {
        int gm = bm + ty*4 + i;
        if (gm >= M) continue;
        #pragma unroll
        for (int j = 0; j < 4; j++) {
            int gn = bn + tx*4 + j;
            if (gn >= N) continue;
            float v = acc[i][j] + bias[gn];
            if (act) v = gelu_tanh(v);
            size_t off = (size_t)gm * N + gn;
            if (addC) v += C[off];
            C[off] = v;
        }
    }
}

// ---------------- tf32 tensor-core GEMM ----------------
// C[M,N] = act(A[M,K] @ W[K,N] + bias) (+= C)
// Requirements: K % 32 == 0, N % 128 == 0. M arbitrary (row-clamped loads,
// predicated stores). CTA 128x128, ktile 32, 256 threads = 8 warps (4x2),
// warp tile 32x64 via m16n8k8 (2 m-tiles x 8 n-tiles).
#define SA_STRIDE 36
#define SB_STRIDE 136
__global__ __launch_bounds__(256)
void gemm_tf32_kernel(const float* __restrict__ A, const float* __restrict__ W,
                      const float* __restrict__ bias, float* __restrict__ C,
                      int M, int K, int N, int act, int addC) {
    __shared__ float sA[128 * SA_STRIDE];   // [m][k] padded
    __shared__ float sB[32 * SB_STRIDE];    // [k][n] padded

    const int tid  = threadIdx.x;
    const int lane = tid & 31;
    const int w    = tid >> 5;
    const int wm   = (w & 3) * 32;
    const int wn   = (w >> 2) * 64;
    const int bm   = blockIdx.y * 128;
    const int bn   = blockIdx.x * 128;

    float acc[2][8][4];
    #pragma unroll
    for (int mt = 0; mt < 2; mt++)
        #pragma unroll
        for (int nt = 0; nt < 8; nt++)
            #pragma unroll
            for (int r = 0; r < 4; r++) acc[mt][nt][r] = 0.f;

    const int ktiles = K >> 5;   // K/32
    float4 ra[4], rb[4];

    // prefetch tile 0
    #pragma unroll
    for (int i = 0; i < 4; i++) {
        int q = tid + 256 * i;
        int row = q >> 3, kq = q & 7;
        int gm = bm + row; if (gm > M - 1) gm = M - 1;
        ra[i] = *reinterpret_cast<const float4*>(&A[(size_t)gm * K + kq * 4]);
        int kr = q >> 5, nq = q & 31;
        rb[i] = *reinterpret_cast<const float4*>(&W[(size_t)kr * N + bn + nq * 4]);
    }

    for (int kt = 0; kt < ktiles; kt++) {
        // stage regs -> smem (with tf32 rounding)
        #pragma unroll
        for (int i = 0; i < 4; i++) {
            int q = tid + 256 * i;
            int row = q >> 3, kq = q & 7;
            float4 a = ra[i];
            a.x = tf32r(a.x); a.y = tf32r(a.y); a.z = tf32r(a.z); a.w = tf32r(a.w);
            *reinterpret_cast<float4*>(&sA[row * SA_STRIDE + kq * 4]) = a;
            int kr = q >> 5, nq = q & 31;
            float4 b = rb[i];
            b.x = tf32r(b.x); b.y = tf32r(b.y); b.z = tf32r(b.z); b.w = tf32r(b.w);
            *reinterpret_cast<float4*>(&sB[kr * SB_STRIDE + nq * 4]) = b;
        }
        __syncthreads();

        // prefetch next tile while computing this one
        if (kt + 1 < ktiles) {
            int k0 = (kt + 1) << 5;
            #pragma unroll
            for (int i = 0; i < 4; i++) {
                int q = tid + 256 * i;
                int row = q >> 3, kq = q & 7;
                int gm = bm + row; if (gm > M - 1) gm = M - 1;
                ra[i] = *reinterpret_cast<const float4*>(&A[(size_t)gm * K + k0 + kq * 4]);
                int kr = q >> 5, nq = q & 31;
                rb[i] = *reinterpret_cast<const float4*>(&W[(size_t)(k0 + kr) * N + bn + nq * 4]);
            }
        }

        // compute 4 k8-steps
        #pragma unroll
        for (int k8 = 0; k8 < 4; k8++) {
            const int kb = k8 * 8;
            unsigned af[2][4], bf[8][2];
            const int arow = wm + (lane >> 2);
            #pragma unroll
            for (int mt = 0; mt < 2; mt++) {
                const float* pa = &sA[(arow + mt * 16) * SA_STRIDE + kb + (lane & 3)];
                af[mt][0] = __float_as_uint(pa[0]);
                af[mt][1] = __float_as_uint(pa[8 * SA_STRIDE]);
                af[mt][2] = __float_as_uint(pa[4]);
                af[mt][3] = __float_as_uint(pa[8 * SA_STRIDE + 4]);
            }
            #pragma unroll
            for (int nt = 0; nt < 8; nt++) {
                const float* pb = &sB[(kb + (lane & 3)) * SB_STRIDE + wn + nt * 8 + (lane >> 2)];
                bf[nt][0] = __float_as_uint(pb[0]);
                bf[nt][1] = __float_as_uint(pb[4 * SB_STRIDE]);
            }
            #pragma unroll
            for (int mt = 0; mt < 2; mt++)
                #pragma unroll
                for (int nt = 0; nt < 8; nt++)
                    mma_tf32(acc[mt][nt], af[mt], bf[nt]);
        }
        __syncthreads();
    }

    // epilogue
    #pragma unroll
    for (int mt = 0; mt < 2; mt++) {
        int rbase = bm + wm + mt * 16 + (lane >> 2);
        #pragma unroll
        for (int half = 0; half < 2; half++) {
            int r = rbase + half * 8;
            if (r >= M) continue;
            #pragma unroll
            for (int nt = 0; nt < 8; nt++) {
                int cix = bn + wn + nt * 8 + 2 * (lane & 3);
                float v0 = acc[mt][nt][half * 2 + 0] + bias[cix];
                float v1 = acc[mt][nt][half * 2 + 1] + bias[cix + 1];
                if (act) { v0 = gelu_tanh(v0); v1 = gelu_tanh(v1); }
                size_t off = (size_t)r * N + cix;
                if (addC) { v0 += C[off]; v1 += C[off + 1]; }
                float2 vv = make_float2(v0, v1);
                *reinterpret_cast<float2*>(&C[off]) = vv;
            }
        }
    }
}

// ---------------- LayerNorm ----------------
__global__ void ln_kernel(const float* __restrict__ x, const float* __restrict__ pos,
                          float* __restrict__ hout, float* __restrict__ hn,
                          const float* __restrict__ w, const float* __restrict__ bb) {
    int row = blockIdx.x;
    int tid = threadIdx.x;       // 128 threads, 3 elems each
    size_t base = (size_t)row * KC;
    float v[3];
    #pragma unroll
    for (int i = 0; i < 3; i++) {
        int c = tid + i * 128;
        float t = x[base + c];
        if (pos) t += pos[base + c];
        v[i] = t;
        if (hout) hout[base + c] = t;
    }
    float s = blockReduceSum(v[0] + v[1] + v[2]);
    float mean = s * (1.0f / KC);
    float d0 = v[0] - mean, d1 = v[1] - mean, d2 = v[2] - mean;
    float s2 = blockReduceSum(d0*d0 + d1*d1 + d2*d2);
    float inv = rsqrtf(s2 * (1.0f / KC) + 1e-5f);
    #pragma unroll
    for (int i = 0; i < 3; i++) {
        int c = tid + i * 128;
        hn[base + c] = (v[i] - mean) * inv * w[c] + bb[c];
    }
}

// ---------------- fused masked flash attention ----------------
__global__ void attn_kernel(const float* __restrict__ qkv,
                            const float* __restrict__ ctr,
                            float* __restrict__ o) {
    const int qt = blockIdx.x, h = blockIdx.y, b = blockIdx.z;
    const int tid = threadIdx.x;
    const int qi = qt * 64 + tid;
    const bool valid = (qi < KV);

    __shared__ __align__(16) float ks[64][64];
    __shared__ __align__(16) float vs[64][64];
    __shared__ float kc[64][3];

    const int qrow = valid ? qi : 0;
    const size_t qbase = ((size_t)b * KV + qrow) * (3*KC) + h * KDH;
    float q[64];
    {
        const float4* q4 = reinterpret_cast<const float4*>(qkv + qbase);
        #pragma unroll
        for (int d4 = 0; d4 < 16; d4++) {
            float4 t = q4[d4];
            q[d4*4+0] = t.x * 0.125f;
            q[d4*4+1] = t.y * 0.125f;
            q[d4*4+2] = t.z * 0.125f;
            q[d4*4+3] = t.w * 0.125f;
        }
    }
    float qc0 = ctr[((size_t)b*KV + qrow)*3 + 0];
    float qc1 = ctr[((size_t)b*KV + qrow)*3 + 1];
    float qc2 = ctr[((size_t)b*KV + qrow)*3 + 2];

    float m = -3.4e38f, l = 0.f;
    float oacc[64];
    #pragma unroll
    for (int d = 0; d < 64; d++) oacc[d] = 0.f;

    const int ntiles = (KV + 63) / 64;
    for (int kt = 0; kt < ntiles; kt++) {
        const int cnt = min(64, KV - kt * 64);
        #pragma unroll 4
        for (int it = 0; it < 16; it++) {
            int idx = tid + it * 64;
            int j  = idx >> 4;
            int d4 = idx & 15;
            if (j < cnt) {
                size_t kb = ((size_t)b * KV + kt*64 + j) * (3*KC) + h * KDH;
                const float4* p4 = reinterpret_cast<const float4*>(qkv);
                float4 kvv = p4[kb/4 + KC/4 + d4];
                float4 vvv = p4[kb/4 + 2*KC/4 + d4];
                reinterpret_cast<float4*>(ks[j])[d4] = kvv;
                reinterpret_cast<float4*>(vs[j])[d4] = vvv;
            }
        }
        if (tid < cnt) {
            size_t cb = ((size_t)b*KV + kt*64 + tid) * 3;
            kc[tid][0] = ctr[cb + 0];
            kc[tid][1] = ctr[cb + 1];
            kc[tid][2] = ctr[cb + 2];
        }
        __syncthreads();

        if (valid) {
            for (int j = 0; j < cnt; j++) {
                float dx = qc0 - kc[j][0];
                float dy = qc1 - kc[j][1];
                float dz = qc2 - kc[j][2];
                float d2 = dx*dx + dy*dy + dz*dz;
                if (d2 < KR2) {
                    const float4* kr = reinterpret_cast<const float4*>(ks[j]);
                    float s0 = 0.f, s1 = 0.f, s2 = 0.f, s3 = 0.f;
                    #pragma unroll
                    for (int d4 = 0; d4 < 16; d4++) {
                        float4 kk = kr[d4];
                        s0 = fmaf(q[d4*4+0], kk.x, s0);
                        s1 = fmaf(q[d4*4+1], kk.y, s1);
                        s2 = fmaf(q[d4*4+2], kk.z, s2);
                        s3 = fmaf(q[d4*4+3], kk.w, s3);
                    }
                    float s = (s0 + s1) + (s2 + s3);
                    if (s > m) {
                        float corr = __expf(m - s);
                        l *= corr;
                        #pragma unroll
                        for (int d = 0; d < 64; d++) oacc[d] *= corr;
                        m = s;
                    }
                    float p = __expf(s - m);
                    l += p;
                    const float4* vr = reinterpret_cast<const float4*>(vs[j]);
                    #pragma unroll
                    for (int d4 = 0; d4 < 16; d4++) {
                        float4 vv = vr[d4];
                        oacc[d4*4+0] = fmaf(p, vv.x, oacc[d4*4+0]);
                        oacc[d4*4+1] = fmaf(p, vv.y, oacc[d4*4+1]);
                        oacc[d4*4+2] = fmaf(p, vv.z, oacc[d4*4+2]);
                        oacc[d4*4+3] = fmaf(p, vv.w, oacc[d4*4+3]);
                    }
                }
            }
        }
        __syncthreads();
    }

    if (valid) {
        float inv = 1.0f / l;
        size_t ob = ((size_t)b*KV + qi) * KC + h * KDH;
        #pragma unroll
        for (int d = 0; d < 64; d++) o[ob + d] = oacc[d] * inv;
    }
}

// ---------------- launcher ----------------
extern "C" void kernel_launch(void* const* d_in, const int* in_sizes, int n_in,
                              void* d_out, int out_size) {
    const float* tokens  = (const float*)d_in[0];
    const float* centers = (const float*)d_in[1];
    const void*  mask    = d_in[2];
    const float* pos_w1  = (const float*)d_in[3];
    const float* pos_b1  = (const float*)d_in[4];
    const float* pos_w2  = (const float*)d_in[5];
    const float* pos_b2  = (const float*)d_in[6];
    const float* ln1_w   = (const float*)d_in[7];
    const float* ln1_b   = (const float*)d_in[8];
    const float* qkv_w   = (const float*)d_in[9];
    const float* qkv_b   = (const float*)d_in[10];
    const float* proj_w  = (const float*)d_in[11];
    const float* proj_b  = (const float*)d_in[12];
    const float* ln2_w   = (const float*)d_in[13];
    const float* ln2_b   = (const float*)d_in[14];
    const float* fc1_w   = (const float*)d_in[15];
    const float* fc1_b   = (const float*)d_in[16];
    const float* fc2_w   = (const float*)d_in[17];
    const float* fc2_b   = (const float*)d_in[18];
    const float* lnf_w   = (const float*)d_in[19];
    const float* lnf_b   = (const float*)d_in[20];

    float *bufA, *bufB, *pos, *hn, *qkv, *obuf, *t4, *ctr;
    int* order;
    cudaGetSymbolAddress((void**)&bufA,  g_bufA);
    cudaGetSymbolAddress((void**)&bufB,  g_bufB);
    cudaGetSymbolAddress((void**)&pos,   g_pos);
    cudaGetSymbolAddress((void**)&hn,    g_hn);
    cudaGetSymbolAddress((void**)&qkv,   g_qkv);
    cudaGetSymbolAddress((void**)&obuf,  g_obuf);
    cudaGetSymbolAddress((void**)&t4,    g_t4);
    cudaGetSymbolAddress((void**)&ctr,   g_ctr);
    cudaGetSymbolAddress((void**)&order, g_order);

    const int M = KBV;                 // 13120
    const dim3 blk(256);
    const int gyT = (M + 127) / 128;   // 103 (tf32 tiles)
    const int gyF = (M + 63) / 64;     // FFMA tiles

    // ragged pack
    build_order_kernel<<<KB, 32>>>(mask, order);
    gather_kernel<<<KBV, KC>>>(tokens, centers, order, bufA, ctr);

    // positional MLP
    gemm_kernel<<<dim3(KC/64, gyF), blk>>>(ctr, pos_w1, pos_b1, hn, M, 3, KC, 1, 0);
    gemm_tf32_kernel<<<dim3(KC/128, gyT), blk>>>(hn, pos_w2, pos_b2, pos, M, KC, KC, 0, 0);

    float* cur = bufA;
    float* oth = bufB;
    for (int l = 0; l < KDEPTH; l++) {
        ln_kernel<<<KBV, 128>>>(cur, pos, oth, hn, ln1_w + l*KC, ln1_b + l*KC);
        gemm_tf32_kernel<<<dim3(3*KC/128, gyT), blk>>>(hn, qkv_w + (size_t)l*KC*3*KC,
                                                       qkv_b + (size_t)l*3*KC, qkv,
                                                       M, KC, 3*KC, 0, 0);
        attn_kernel<<<dim3((KV+63)/64, KH, KB), 64>>>(qkv, ctr, obuf);
        gemm_tf32_kernel<<<dim3(KC/128, gyT), blk>>>(obuf, proj_w + (size_t)l*KC*KC,
                                                     proj_b + (size_t)l*KC, oth,
                                                     M, KC, KC, 0, 1);
        ln_kernel<<<KBV, 128>>>(oth, nullptr, nullptr, hn, ln2_w + l*KC, ln2_b + l*KC);
        gemm_tf32_kernel<<<dim3(4*KC/128, gyT), blk>>>(hn, fc1_w + (size_t)l*KC*4*KC,
                                                       fc1_b + (size_t)l*4*KC, t4,
                                                       M, KC, 4*KC, 1, 0);
        gemm_tf32_kernel<<<dim3(KC/128, gyT), blk>>>(t4, fc2_w + (size_t)l*4*KC*KC,
                                                     fc2_b + (size_t)l*KC, oth,
                                                     M, 4*KC, KC, 0, 1);
        float* tmp = cur; cur = oth; oth = tmp;
    }
    ln_kernel<<<KBV, 128>>>(cur, nullptr, nullptr, (float*)d_out, lnf_w, lnf_b);
}